// round 15
// baseline (speedup 1.0000x reference)
#include <cuda_runtime.h>
#include <cuda_bf16.h>
#include <math.h>

typedef unsigned long long u64;
typedef unsigned int u32;

// ---------------------------------------------------------------------------
// Scratch (allocation-free: __device__ globals)
// ---------------------------------------------------------------------------
#define MAXN 4096
__device__ __align__(16) __nv_bfloat16 g_h1bf[MAXN * 196 * 64]; // conv1 out [n][pos196][hi32|lo32]
__device__ __align__(16) float g_h2[MAXN * 3136];               // conv2 out [n][pos49*64+co]
__device__ __align__(16) float g_fcw[3136 * 32];                // fc_w transposed [pos*64+co][d]
__device__ __align__(16) __nv_bfloat16 g_w2bf[2 * 9 * 32 * 64]; // conv2 w, swizzled

// ---------------------------------------------------------------------------
// Helpers
// ---------------------------------------------------------------------------
__device__ __forceinline__ u32 smem_to_u32(const void* p) {
    u32 a;
    asm("{ .reg .u64 t; cvta.to.shared.u64 t, %1; cvt.u32.u64 %0, t; }"
        : "=r"(a) : "l"(p));
    return a;
}
__device__ __forceinline__ void ldsm_x4(u32* r, u32 addr) {
    asm volatile("ldmatrix.sync.aligned.m8n8.x4.shared.b16 {%0,%1,%2,%3}, [%4];"
        : "=r"(r[0]), "=r"(r[1]), "=r"(r[2]), "=r"(r[3]) : "r"(addr));
}
__device__ __forceinline__ void ldsm_x4_t(u32* r, u32 addr) {
    asm volatile("ldmatrix.sync.aligned.m8n8.x4.trans.shared.b16 {%0,%1,%2,%3}, [%4];"
        : "=r"(r[0]), "=r"(r[1]), "=r"(r[2]), "=r"(r[3]) : "r"(addr));
}
__device__ __forceinline__ void mma_bf16(float* c, const u32* a, const u32* b) {
    asm volatile(
        "mma.sync.aligned.m16n8k16.row.col.f32.bf16.bf16.f32 "
        "{%0,%1,%2,%3}, {%4,%5,%6,%7}, {%8,%9}, {%0,%1,%2,%3};"
        : "+f"(c[0]), "+f"(c[1]), "+f"(c[2]), "+f"(c[3])
        : "r"(a[0]), "r"(a[1]), "r"(a[2]), "r"(a[3]), "r"(b[0]), "r"(b[1]));
}
// packed f32x2
__device__ __forceinline__ u64 pack2(float lo, float hi) {
    u64 r;
    asm("mov.b64 %0, {%1, %2};" : "=l"(r) : "f"(lo), "f"(hi));
    return r;
}
__device__ __forceinline__ void unpack2(u64 v, float& lo, float& hi) {
    asm("mov.b64 {%0, %1}, %2;" : "=f"(lo), "=f"(hi) : "l"(v));
}
__device__ __forceinline__ u64 dup2(float v) { return pack2(v, v); }
__device__ __forceinline__ u64 fma2(u64 a, u64 b, u64 c) {
    u64 r;
    asm("fma.rn.f32x2 %0, %1, %2, %3;" : "=l"(r) : "l"(a), "l"(b), "l"(c));
    return r;
}

// ---------------------------------------------------------------------------
// Kernel 1: conv1 (1->32, 3x3, pad 1) + relu + maxpool2 -> bf16 hi/lo
// thread = (pos, co-half): 392 active threads, 8 channel-pairs each.
// Patch loaded once per (pos,half) instead of once per (pos,pair).
// ---------------------------------------------------------------------------
#define C1_THREADS 416

__global__ __launch_bounds__(C1_THREADS)
void conv1_kernel(const float* __restrict__ x,
                  const float* __restrict__ w,
                  const float* __restrict__ bias)
{
    __shared__ __align__(16) float s_in[30 * 30];
    __shared__ __align__(16) float s_w[9 * 32];
    __shared__ float s_b[32];

    const int n   = blockIdx.x;
    const int tid = threadIdx.x;

    for (int i = tid; i < 900; i += C1_THREADS) s_in[i] = 0.0f;
    for (int i = tid; i < 288; i += C1_THREADS) {
        int co = i / 9, k = i % 9;
        s_w[k * 32 + co] = w[co * 9 + k];
    }
    if (tid < 32) s_b[tid] = bias[tid];
    __syncthreads();

    const float* xb = x + (size_t)n * 784;
    for (int i = tid; i < 784; i += C1_THREADS) {
        int y = i / 28, c = i % 28;
        s_in[(y + 1) * 30 + (c + 1)] = xb[i];
    }
    __syncthreads();

    if (tid < 392) {
        const int pos  = tid >> 1;          // 0..195
        const int half = tid & 1;           // pairs half*8 .. half*8+7
        const int py   = pos / 14;
        const int px   = pos - py * 14;

        // 4x4 patch once
        float pv[4][4];
#pragma unroll
        for (int r = 0; r < 4; r++)
#pragma unroll
            for (int c = 0; c < 4; c++)
                pv[r][c] = s_in[(2 * py + r) * 30 + (2 * px + c)];

        const float2* s_w2 = reinterpret_cast<const float2*>(s_w);
        u64 acc[8][4];
#pragma unroll
        for (int p = 0; p < 8; p++) {
            u64 b0 = pack2(s_b[(half * 8 + p) * 2], s_b[(half * 8 + p) * 2 + 1]);
            acc[p][0] = b0; acc[p][1] = b0; acc[p][2] = b0; acc[p][3] = b0;
        }

#pragma unroll
        for (int ky = 0; ky < 3; ky++)
#pragma unroll
            for (int kx = 0; kx < 3; kx++) {
                const int tap = ky * 3 + kx;
                u64 d0 = dup2(pv[ky][kx]);
                u64 d1 = dup2(pv[ky][kx + 1]);
                u64 d2 = dup2(pv[ky + 1][kx]);
                u64 d3 = dup2(pv[ky + 1][kx + 1]);
#pragma unroll
                for (int p = 0; p < 8; p++) {
                    float2 wf = s_w2[tap * 16 + half * 8 + p];
                    u64 wv = pack2(wf.x, wf.y);
                    acc[p][0] = fma2(d0, wv, acc[p][0]);
                    acc[p][1] = fma2(d1, wv, acc[p][1]);
                    acc[p][2] = fma2(d2, wv, acc[p][2]);
                    acc[p][3] = fma2(d3, wv, acc[p][3]);
                }
            }

        __nv_bfloat162 hi8[8], lo8[8];
#pragma unroll
        for (int p = 0; p < 8; p++) {
            float l0, h0, l1, h1, l2, h2, l3, h3;
            unpack2(acc[p][0], l0, h0); unpack2(acc[p][1], l1, h1);
            unpack2(acc[p][2], l2, h2); unpack2(acc[p][3], l3, h3);
            float mlo = fmaxf(fmaxf(fmaxf(l0, l1), fmaxf(l2, l3)), 0.0f);
            float mhi = fmaxf(fmaxf(fmaxf(h0, h1), fmaxf(h2, h3)), 0.0f);
            __nv_bfloat16 hx = __float2bfloat16(mlo);
            __nv_bfloat16 hy = __float2bfloat16(mhi);
            hi8[p].x = hx; hi8[p].y = hy;
            lo8[p].x = __float2bfloat16(mlo - __bfloat162float(hx));
            lo8[p].y = __float2bfloat16(mhi - __bfloat162float(hy));
        }

        // store: hi pairs at [pos*32 + half*8 + p], lo at +16. (uint4 = 4 pairs)
        uint4* ob = reinterpret_cast<uint4*>(g_h1bf) + (size_t)n * 1568;
        const uint4* hsrc = reinterpret_cast<const uint4*>(hi8);
        const uint4* lsrc = reinterpret_cast<const uint4*>(lo8);
        ob[pos * 8 + half * 2 + 0]     = hsrc[0];
        ob[pos * 8 + half * 2 + 1]     = hsrc[1];
        ob[pos * 8 + 4 + half * 2 + 0] = lsrc[0];
        ob[pos * 8 + 4 + half * 2 + 1] = lsrc[1];
    }
}

// ---------------------------------------------------------------------------
// Prep (merged): conv2 weights -> bf16 hi/lo swizzled; fc_w transpose
// grid: 104 blocks x 1024
// ---------------------------------------------------------------------------
__global__ void prep_all(const float* __restrict__ w2,
                         const float* __restrict__ fw)
{
    int idx = blockIdx.x * 1024 + threadIdx.x;
    if (idx < 4608) {
        int chunk = idx & 7;
        int row   = idx >> 3;
        int k     = row & 31;
        int tap   = (row >> 5) % 9;
        int p     = row / 288;
        __nv_bfloat16 vals[8];
#pragma unroll
        for (int j = 0; j < 8; j++) {
            int co = chunk * 8 + j;
            float v = w2[co * 288 + k * 9 + tap];
            __nv_bfloat16 h = __float2bfloat16(v);
            vals[j] = p ? __float2bfloat16(v - __bfloat162float(h)) : h;
        }
        char* base = reinterpret_cast<char*>(g_w2bf);
        *reinterpret_cast<uint4*>(base + row * 128 + ((chunk ^ (k & 7)) << 4)) =
            *reinterpret_cast<const uint4*>(vals);
    } else {
        int t = idx - 4608;
        if (t < 3136 * 32) {
            int kp = t >> 5, d = t & 31;
            int pos = kp >> 6, co = kp & 63;
            g_fcw[t] = fw[d * 3136 + co * 49 + pos];
        }
    }
}

// ---------------------------------------------------------------------------
// Kernel 2: conv2 warp-MMA (R14 config — frozen). 448 threads / 14 warps,
// warp = (row r, n-half h), 2 CTAs/SM, 7 active warps/SMSP.
// SMEM: bias @0; A @1024 (290x128B); B @38144 (576x128B). Total 111872 B.
// ---------------------------------------------------------------------------
#define C2_BIAS_OFF 0
#define C2_A_OFF    1024
#define C2_B_OFF    (1024 + 290 * 128)            // 38144
#define C2_SMEM_BYTES (C2_B_OFF + 576 * 128)      // 111872
#define C2_THREADS  448

__global__ __launch_bounds__(C2_THREADS, 2)
void conv2_mma_kernel(const float* __restrict__ bias, int N)
{
    extern __shared__ __align__(16) char smem[];
    const u32 sb   = smem_to_u32(smem);
    const int tid  = threadIdx.x;
    const int wrp  = tid >> 5;
    const int r    = wrp % 7;
    const int h    = wrp / 7;
    const u32 lane = tid & 31;
    const u32 lrow = lane & 15, lsel = lane >> 4;
    const int g    = (int)(lane >> 2);
    const int kq   = (int)(lane & 3);

    float* s_bias = reinterpret_cast<float*>(smem + C2_BIAS_OFF);
    if (tid < 64) s_bias[tid] = bias[tid];

    for (int i = tid; i < 2320; i += C2_THREADS)
        reinterpret_cast<uint4*>(smem + C2_A_OFF)[i] = make_uint4(0, 0, 0, 0);
    for (int i = tid; i < 4608; i += C2_THREADS)
        reinterpret_cast<uint4*>(smem + C2_B_OFF)[i] =
            reinterpret_cast<const uint4*>(g_w2bf)[i];
    __syncthreads();

    const u32 Bbase = sb + C2_B_OFF;
    const u32 Abase = sb + C2_A_OFF;

    for (int img = blockIdx.x; img < N; img += (int)gridDim.x) {
        const uint4* src = reinterpret_cast<const uint4*>(g_h1bf + (size_t)img * 12544);
        for (int i = tid; i < 1568; i += C2_THREADS) {
            int pos = i >> 3, chunk = i & 7;
            int py = pos / 14, px = pos - py * 14;
            int row = (py + 1) * 16 + (px + 1) + 17;
            *reinterpret_cast<uint4*>(smem + C2_A_OFF + row * 128 +
                                      ((chunk ^ (row & 7)) << 4)) = src[i];
        }
        __syncthreads();

        {
            float C[2][4][4];
#pragma unroll
            for (int mt = 0; mt < 2; mt++)
#pragma unroll
                for (int nt = 0; nt < 4; nt++)
#pragma unroll
                    for (int q = 0; q < 4; q++) C[mt][nt][q] = 0.0f;

#pragma unroll 1
            for (int tap = 0; tap < 9; tap++) {
                const u32 rowoff = (u32)((tap / 3) * 16 + (tap % 3));
#pragma unroll
                for (int s = 0; s < 2; s++) {
                    u32 bh[2][4];
#pragma unroll
                    for (int j = 0; j < 2; j++) {
                        u32 krow = (u32)(tap * 32 + s * 16) + lrow;
                        u32 bchunk = (u32)((h * 2 + j) * 2) + lsel;
                        ldsm_x4_t(bh[j], Bbase + krow * 128 + ((bchunk ^ (krow & 7)) << 4));
                    }
                    u32 ah[2][4];
#pragma unroll
                    for (int mt = 0; mt < 2; mt++) {
                        u32 arow = (u32)((2 * r + 1 + mt) * 16) + lrow + rowoff;
                        u32 achunk = (u32)(s * 2) + lsel;
                        ldsm_x4(ah[mt], Abase + arow * 128 + ((achunk ^ (arow & 7)) << 4));
                    }
#pragma unroll
                    for (int mt = 0; mt < 2; mt++)
#pragma unroll
                        for (int nt = 0; nt < 4; nt++)
                            mma_bf16(C[mt][nt], ah[mt], &bh[nt >> 1][(nt & 1) * 2]);
                    {
                        u32 bl[2][4];
#pragma unroll
                        for (int j = 0; j < 2; j++) {
                            u32 krow = 288u + (u32)(tap * 32 + s * 16) + lrow;
                            u32 bchunk = (u32)((h * 2 + j) * 2) + lsel;
                            ldsm_x4_t(bl[j], Bbase + krow * 128 + ((bchunk ^ (krow & 7)) << 4));
                        }
#pragma unroll
                        for (int mt = 0; mt < 2; mt++)
#pragma unroll
                            for (int nt = 0; nt < 4; nt++)
                                mma_bf16(C[mt][nt], ah[mt], &bl[nt >> 1][(nt & 1) * 2]);
                    }
                    {
                        u32 al[2][4];
#pragma unroll
                        for (int mt = 0; mt < 2; mt++) {
                            u32 arow = (u32)((2 * r + 1 + mt) * 16) + lrow + rowoff;
                            u32 achunk = 4u + (u32)(s * 2) + lsel;
                            ldsm_x4(al[mt], Abase + arow * 128 + ((achunk ^ (arow & 7)) << 4));
                        }
#pragma unroll
                        for (int mt = 0; mt < 2; mt++)
#pragma unroll
                            for (int nt = 0; nt < 4; nt++)
                                mma_bf16(C[mt][nt], al[mt], &bh[nt >> 1][(nt & 1) * 2]);
                    }
                }
            }

            float* outb = g_h2 + (size_t)img * 3136;
#pragma unroll
            for (int nt = 0; nt < 4; nt++) {
                const int ch = h * 32 + nt * 8 + 2 * kq;
                float p0 = fmaxf(C[0][nt][0], C[1][nt][0]);
                float p1 = fmaxf(C[0][nt][1], C[1][nt][1]);
                float p2 = fmaxf(C[0][nt][2], C[1][nt][2]);
                float p3 = fmaxf(C[0][nt][3], C[1][nt][3]);
                int srcl = (int)((lane + 4) & 31);
                float q0 = __shfl_sync(0xffffffffu, p0, srcl);
                float q1 = __shfl_sync(0xffffffffu, p1, srcl);
                float q2 = __shfl_sync(0xffffffffu, p2, srcl);
                float q3 = __shfl_sync(0xffffffffu, p3, srcl);
                float bx = s_bias[ch];
                float by = s_bias[ch + 1];

                if (g == 1 || g == 3 || g == 5) {
                    int pxo = (g - 1) >> 1;
                    float2 r0;
                    r0.x = fmaxf(fmaxf(p0, q0) + bx, 0.0f);
                    r0.y = fmaxf(fmaxf(p1, q1) + by, 0.0f);
                    *reinterpret_cast<float2*>(outb + (r * 7 + pxo) * 64 + ch) = r0;
                    float2 r1;
                    r1.x = fmaxf(fmaxf(p2, q2) + bx, 0.0f);
                    r1.y = fmaxf(fmaxf(p3, q3) + by, 0.0f);
                    *reinterpret_cast<float2*>(outb + (r * 7 + pxo + 4) * 64 + ch) = r1;
                } else if (g == 7) {
                    float2 r0;
                    r0.x = fmaxf(fmaxf(p0, q2) + bx, 0.0f);
                    r0.y = fmaxf(fmaxf(p1, q3) + by, 0.0f);
                    *reinterpret_cast<float2*>(outb + (r * 7 + 3) * 64 + ch) = r0;
                }
            }
        }
        __syncthreads();
    }
}

// ---------------------------------------------------------------------------
// Kernel 3: fused FC + hyperbolic MLR.
// ---------------------------------------------------------------------------
#define FC_KT 112
#define FC_NB 16

__global__ __launch_bounds__(256)
void fc_mlr_kernel(const float* __restrict__ bias,
                   const float* __restrict__ hw,
                   const float* __restrict__ hb,
                   float* __restrict__ out)
{
    __shared__ __align__(16) float a_s[FC_NB * FC_KT];
    __shared__ float b_s[FC_KT * 33];
    __shared__ float x_s[FC_NB * 33];
    __shared__ float hw_s[320];
    __shared__ float hb_s[320];

    const int tid = threadIdx.x;
    const int n0  = blockIdx.x * FC_NB;
    const int d   = tid & 31;
    const int tr  = tid >> 5;

    for (int i = tid; i < 320; i += 256) { hw_s[i] = hw[i]; hb_s[i] = hb[i]; }

    float acc[2];
    float bv = bias[d];
    acc[0] = bv; acc[1] = bv;

    for (int kt = 0; kt < 3136; kt += FC_KT) {
        __syncthreads();
        for (int i = tid; i < FC_NB * FC_KT; i += 256) {
            int rr = i / FC_KT, c = i - rr * FC_KT;
            a_s[rr * FC_KT + c] = g_h2[(size_t)(n0 + rr) * 3136 + kt + c];
        }
        for (int i = tid; i < 32 * FC_KT; i += 256) {
            int c = i >> 5, dd = i & 31;
            b_s[c * 33 + dd] = g_fcw[(size_t)(kt + c) * 32 + dd];
        }
        __syncthreads();

#pragma unroll 4
        for (int kk = 0; kk < FC_KT; kk += 4) {
            float w0 = b_s[(kk + 0) * 33 + d];
            float w1 = b_s[(kk + 1) * 33 + d];
            float w2 = b_s[(kk + 2) * 33 + d];
            float w3 = b_s[(kk + 3) * 33 + d];
#pragma unroll
            for (int i = 0; i < 2; i++) {
                float4 av = *reinterpret_cast<const float4*>(
                    a_s + (tr * 2 + i) * FC_KT + kk);
                acc[i] = fmaf(av.x, w0, acc[i]);
                acc[i] = fmaf(av.y, w1, acc[i]);
                acc[i] = fmaf(av.z, w2, acc[i]);
                acc[i] = fmaf(av.w, w3, acc[i]);
            }
        }
    }

    x_s[(tr * 2 + 0) * 33 + d] = acc[0];
    x_s[(tr * 2 + 1) * 33 + d] = acc[1];
    __syncthreads();

    if (tid < 160) {
        int n = tid / 10;
        int k = tid - n * 10;
        const float* xv = x_s + n * 33;
        const float* wv = hw_s + k * 32;
        const float* bvv = hb_s + k * 32;

        float x2 = 0.f, b2 = 0.f, w2 = 0.f, xb = 0.f, xw = 0.f, wb = 0.f;
#pragma unroll
        for (int j = 0; j < 32; j++) {
            float xj = xv[j], wj = wv[j], bj = bvv[j];
            x2 += xj * xj;  b2 += bj * bj;  w2 += wj * wj;
            xb += xj * bj;  xw += xj * wj;  wb += wj * bj;
        }

        const float EPSf = 1e-5f;
        const float MN   = 0.99999f;

        float inner  = -xb;
        float w_norm = sqrtf(w2);
        float inv_wn = 1.0f / fmaxf(w_norm, 1e-12f);
        float wb_n   = -wb * inv_wn;
        float xw_n   = xw * inv_wn;

        float a_num = 1.0f + 2.0f * inner + x2;
        float b_num = 1.0f - b2;
        float denom = 1.0f + 2.0f * inner + x2 * b2;
        float alpha = a_num / fmaxf(denom, EPSf);
        float beta  = b_num / denom;
        float mob2  = alpha * alpha * b2 + 2.0f * alpha * beta * inner
                    + beta * beta * x2;
        float sq    = sqrtf(mob2);
        float normalizer = (sq > MN) ? (MN / fmaxf(sq, EPSf)) : 1.0f;
        float mob2f = (sq < MN) ? mob2 : (MN * MN);
        float hyp   = (alpha * wb_n + beta * xw_n) * normalizer;
        float asin_in = 2.0f * hyp / fmaxf(1.0f - mob2f, EPSf);

        out[(size_t)(n0 + n) * 10 + k] =
            (2.0f / fmaxf(1.0f - b2, EPSf)) * w_norm * asinhf(asin_in);
    }
}

// ---------------------------------------------------------------------------
// Launch
// ---------------------------------------------------------------------------
extern "C" void kernel_launch(void* const* d_in, const int* in_sizes, int n_in,
                              void* d_out, int out_size) {
    const float* x   = (const float*)d_in[0];
    const float* w1  = (const float*)d_in[1];
    const float* b1  = (const float*)d_in[2];
    const float* w2  = (const float*)d_in[3];
    const float* b2  = (const float*)d_in[4];
    const float* fw  = (const float*)d_in[5];
    const float* fb  = (const float*)d_in[6];
    const float* hw  = (const float*)d_in[7];
    const float* hb  = (const float*)d_in[8];
    float* out = (float*)d_out;

    const int N = in_sizes[0] / 784;

    cudaFuncSetAttribute(conv2_mma_kernel,
                         cudaFuncAttributeMaxDynamicSharedMemorySize,
                         C2_SMEM_BYTES);

    prep_all<<<104, 1024>>>(w2, fw);
    conv1_kernel<<<N, C1_THREADS>>>(x, w1, b1);
    int g2 = N < 296 ? N : 296;
    conv2_mma_kernel<<<g2, C2_THREADS, C2_SMEM_BYTES>>>(b2, N);
    fc_mlr_kernel<<<N / FC_NB, 256>>>(fb, hw, hb, out);
}

// round 16
// speedup vs baseline: 1.1884x; 1.1884x over previous
#include <cuda_runtime.h>
#include <cuda_bf16.h>
#include <math.h>

typedef unsigned long long u64;
typedef unsigned int u32;

// ---------------------------------------------------------------------------
// Scratch (allocation-free: __device__ globals)
// ---------------------------------------------------------------------------
#define MAXN 4096
__device__ __align__(16) __nv_bfloat16 g_h1bf[MAXN * 196 * 64]; // conv1 out [n][pos196][hi32|lo32]
__device__ __align__(16) __nv_bfloat16 g_xhi[MAXN * 3136];      // conv2 out hi plane [n][pos*64+co]
__device__ __align__(16) __nv_bfloat16 g_xlo[MAXN * 3136];      // conv2 out lo plane
__device__ __align__(16) __nv_bfloat16 g_fcwbf[3136 * 64];      // fc w [k'][Whi32|Wlo32], swizzled
__device__ __align__(16) __nv_bfloat16 g_w2bf[2 * 9 * 32 * 64]; // conv2 w, swizzled

// ---------------------------------------------------------------------------
// Helpers
// ---------------------------------------------------------------------------
__device__ __forceinline__ u32 smem_to_u32(const void* p) {
    u32 a;
    asm("{ .reg .u64 t; cvta.to.shared.u64 t, %1; cvt.u32.u64 %0, t; }"
        : "=r"(a) : "l"(p));
    return a;
}
__device__ __forceinline__ void ldsm_x4(u32* r, u32 addr) {
    asm volatile("ldmatrix.sync.aligned.m8n8.x4.shared.b16 {%0,%1,%2,%3}, [%4];"
        : "=r"(r[0]), "=r"(r[1]), "=r"(r[2]), "=r"(r[3]) : "r"(addr));
}
__device__ __forceinline__ void ldsm_x4_t(u32* r, u32 addr) {
    asm volatile("ldmatrix.sync.aligned.m8n8.x4.trans.shared.b16 {%0,%1,%2,%3}, [%4];"
        : "=r"(r[0]), "=r"(r[1]), "=r"(r[2]), "=r"(r[3]) : "r"(addr));
}
__device__ __forceinline__ void mma_bf16(float* c, const u32* a, const u32* b) {
    asm volatile(
        "mma.sync.aligned.m16n8k16.row.col.f32.bf16.bf16.f32 "
        "{%0,%1,%2,%3}, {%4,%5,%6,%7}, {%8,%9}, {%0,%1,%2,%3};"
        : "+f"(c[0]), "+f"(c[1]), "+f"(c[2]), "+f"(c[3])
        : "r"(a[0]), "r"(a[1]), "r"(a[2]), "r"(a[3]), "r"(b[0]), "r"(b[1]));
}
// packed f32x2
__device__ __forceinline__ u64 pack2(float lo, float hi) {
    u64 r;
    asm("mov.b64 %0, {%1, %2};" : "=l"(r) : "f"(lo), "f"(hi));
    return r;
}
__device__ __forceinline__ void unpack2(u64 v, float& lo, float& hi) {
    asm("mov.b64 {%0, %1}, %2;" : "=f"(lo), "=f"(hi) : "l"(v));
}
__device__ __forceinline__ u64 dup2(float v) { return pack2(v, v); }
__device__ __forceinline__ u64 fma2(u64 a, u64 b, u64 c) {
    u64 r;
    asm("fma.rn.f32x2 %0, %1, %2, %3;" : "=l"(r) : "l"(a), "l"(b), "l"(c));
    return r;
}
__device__ __forceinline__ __nv_bfloat162 bf2_hi(float x, float y,
                                                 __nv_bfloat162& lo) {
    __nv_bfloat162 h;
    h.x = __float2bfloat16(x);
    h.y = __float2bfloat16(y);
    lo.x = __float2bfloat16(x - __bfloat162float(h.x));
    lo.y = __float2bfloat16(y - __bfloat162float(h.y));
    return h;
}

// ---------------------------------------------------------------------------
// Kernel 1: conv1 (1->32, 3x3, pad 1) + relu + maxpool2 -> bf16 hi/lo
// (R14 version — proven)
// ---------------------------------------------------------------------------
__global__ __launch_bounds__(256)
void conv1_kernel(const float* __restrict__ x,
                  const float* __restrict__ w,
                  const float* __restrict__ bias)
{
    __shared__ __align__(16) float s_in[30 * 30];
    __shared__ __align__(16) float s_w[9 * 32];
    __shared__ float s_b[32];

    const int n   = blockIdx.x;
    const int tid = threadIdx.x;

    for (int i = tid; i < 900; i += 256) s_in[i] = 0.0f;
    for (int i = tid; i < 288; i += 256) {
        int co = i / 9, k = i % 9;
        s_w[k * 32 + co] = w[co * 9 + k];
    }
    if (tid < 32) s_b[tid] = bias[tid];
    __syncthreads();

    const float* xb = x + (size_t)n * 784;
    for (int i = tid; i < 784; i += 256) {
        int y = i / 28, c = i % 28;
        s_in[(y + 1) * 30 + (c + 1)] = xb[i];
    }
    __syncthreads();

    const float2* s_w2 = reinterpret_cast<const float2*>(s_w);
    __nv_bfloat162* ob = reinterpret_cast<__nv_bfloat162*>(g_h1bf) + (size_t)n * 6272;

    for (int it = tid; it < 3136; it += 256) {
        const int pair = it & 15;
        const int pos  = it >> 4;
        const int py   = pos / 14;
        const int px   = pos - py * 14;

        float pv[4][4];
#pragma unroll
        for (int r = 0; r < 4; r++)
#pragma unroll
            for (int c = 0; c < 4; c++)
                pv[r][c] = s_in[(2 * py + r) * 30 + (2 * px + c)];

        u64 binit = pack2(s_b[pair * 2], s_b[pair * 2 + 1]);
        u64 acc[4] = {binit, binit, binit, binit};

#pragma unroll
        for (int ky = 0; ky < 3; ky++)
#pragma unroll
            for (int kx = 0; kx < 3; kx++) {
                float2 wf = s_w2[(ky * 3 + kx) * 16 + pair];
                u64 wv = pack2(wf.x, wf.y);
                acc[0] = fma2(dup2(pv[ky][kx]),         wv, acc[0]);
                acc[1] = fma2(dup2(pv[ky][kx + 1]),     wv, acc[1]);
                acc[2] = fma2(dup2(pv[ky + 1][kx]),     wv, acc[2]);
                acc[3] = fma2(dup2(pv[ky + 1][kx + 1]), wv, acc[3]);
            }

        float l0, h0, l1, h1, l2, h2, l3, h3;
        unpack2(acc[0], l0, h0); unpack2(acc[1], l1, h1);
        unpack2(acc[2], l2, h2); unpack2(acc[3], l3, h3);
        float mlo = fmaxf(fmaxf(fmaxf(l0, l1), fmaxf(l2, l3)), 0.0f);
        float mhi = fmaxf(fmaxf(fmaxf(h0, h1), fmaxf(h2, h3)), 0.0f);

        __nv_bfloat162 lv;
        __nv_bfloat162 hv = bf2_hi(mlo, mhi, lv);
        ob[pos * 32 + pair]      = hv;
        ob[pos * 32 + 16 + pair] = lv;
    }
}

// ---------------------------------------------------------------------------
// Prep (merged): conv2 weights + fc weights -> bf16 hi/lo swizzled
// grid: 29 blocks x 1024  (4608 w2 items + 25088 fcw items)
// ---------------------------------------------------------------------------
__global__ void prep_all(const float* __restrict__ w2,
                         const float* __restrict__ fw)
{
    int idx = blockIdx.x * 1024 + threadIdx.x;
    if (idx < 4608) {
        int chunk = idx & 7;
        int row   = idx >> 3;
        int k     = row & 31;
        int tap   = (row >> 5) % 9;
        int p     = row / 288;
        __nv_bfloat16 vals[8];
#pragma unroll
        for (int j = 0; j < 8; j++) {
            int co = chunk * 8 + j;
            float v = w2[co * 288 + k * 9 + tap];
            __nv_bfloat16 h = __float2bfloat16(v);
            vals[j] = p ? __float2bfloat16(v - __bfloat162float(h)) : h;
        }
        char* base = reinterpret_cast<char*>(g_w2bf);
        *reinterpret_cast<uint4*>(base + row * 128 + ((chunk ^ (k & 7)) << 4)) =
            *reinterpret_cast<const uint4*>(vals);
    } else {
        int t = idx - 4608;                 // 0 .. 25087
        if (t < 3136 * 8) {
            int chunk = t & 7;              // 0..3 = hi, 4..7 = lo
            int kp    = t >> 3;             // k' = pos*64+co
            int pos   = kp >> 6, co = kp & 63;
            int hilo  = chunk >> 2;
            __nv_bfloat16 vals[8];
#pragma unroll
            for (int j = 0; j < 8; j++) {
                int d = (chunk & 3) * 8 + j;
                float v = fw[d * 3136 + co * 49 + pos];
                __nv_bfloat16 h = __float2bfloat16(v);
                vals[j] = hilo ? __float2bfloat16(v - __bfloat162float(h)) : h;
            }
            char* base = reinterpret_cast<char*>(g_fcwbf);
            *reinterpret_cast<uint4*>(base + kp * 128 + ((chunk ^ (kp & 7)) << 4)) =
                *reinterpret_cast<const uint4*>(vals);
        }
    }
}

// ---------------------------------------------------------------------------
// Kernel 2: conv2 warp-MMA (R14 config — frozen math), epilogue now emits
// bf16 hi/lo planes for the FC GEMM.
// ---------------------------------------------------------------------------
#define C2_BIAS_OFF 0
#define C2_A_OFF    1024
#define C2_B_OFF    (1024 + 290 * 128)            // 38144
#define C2_SMEM_BYTES (C2_B_OFF + 576 * 128)      // 111872
#define C2_THREADS  448

__global__ __launch_bounds__(C2_THREADS, 2)
void conv2_mma_kernel(const float* __restrict__ bias, int N)
{
    extern __shared__ __align__(16) char smem[];
    const u32 sb   = smem_to_u32(smem);
    const int tid  = threadIdx.x;
    const int wrp  = tid >> 5;
    const int r    = wrp % 7;
    const int h    = wrp / 7;
    const u32 lane = tid & 31;
    const u32 lrow = lane & 15, lsel = lane >> 4;
    const int g    = (int)(lane >> 2);
    const int kq   = (int)(lane & 3);

    float* s_bias = reinterpret_cast<float*>(smem + C2_BIAS_OFF);
    if (tid < 64) s_bias[tid] = bias[tid];

    for (int i = tid; i < 2320; i += C2_THREADS)
        reinterpret_cast<uint4*>(smem + C2_A_OFF)[i] = make_uint4(0, 0, 0, 0);
    for (int i = tid; i < 4608; i += C2_THREADS)
        reinterpret_cast<uint4*>(smem + C2_B_OFF)[i] =
            reinterpret_cast<const uint4*>(g_w2bf)[i];
    __syncthreads();

    const u32 Bbase = sb + C2_B_OFF;
    const u32 Abase = sb + C2_A_OFF;

    for (int img = blockIdx.x; img < N; img += (int)gridDim.x) {
        const uint4* src = reinterpret_cast<const uint4*>(g_h1bf + (size_t)img * 12544);
        for (int i = tid; i < 1568; i += C2_THREADS) {
            int pos = i >> 3, chunk = i & 7;
            int py = pos / 14, px = pos - py * 14;
            int row = (py + 1) * 16 + (px + 1) + 17;
            *reinterpret_cast<uint4*>(smem + C2_A_OFF + row * 128 +
                                      ((chunk ^ (row & 7)) << 4)) = src[i];
        }
        __syncthreads();

        {
            float C[2][4][4];
#pragma unroll
            for (int mt = 0; mt < 2; mt++)
#pragma unroll
                for (int nt = 0; nt < 4; nt++)
#pragma unroll
                    for (int q = 0; q < 4; q++) C[mt][nt][q] = 0.0f;

#pragma unroll 1
            for (int tap = 0; tap < 9; tap++) {
                const u32 rowoff = (u32)((tap / 3) * 16 + (tap % 3));
#pragma unroll
                for (int s = 0; s < 2; s++) {
                    u32 bh[2][4];
#pragma unroll
                    for (int j = 0; j < 2; j++) {
                        u32 krow = (u32)(tap * 32 + s * 16) + lrow;
                        u32 bchunk = (u32)((h * 2 + j) * 2) + lsel;
                        ldsm_x4_t(bh[j], Bbase + krow * 128 + ((bchunk ^ (krow & 7)) << 4));
                    }
                    u32 ah[2][4];
#pragma unroll
                    for (int mt = 0; mt < 2; mt++) {
                        u32 arow = (u32)((2 * r + 1 + mt) * 16) + lrow + rowoff;
                        u32 achunk = (u32)(s * 2) + lsel;
                        ldsm_x4(ah[mt], Abase + arow * 128 + ((achunk ^ (arow & 7)) << 4));
                    }
#pragma unroll
                    for (int mt = 0; mt < 2; mt++)
#pragma unroll
                        for (int nt = 0; nt < 4; nt++)
                            mma_bf16(C[mt][nt], ah[mt], &bh[nt >> 1][(nt & 1) * 2]);
                    {
                        u32 bl[2][4];
#pragma unroll
                        for (int j = 0; j < 2; j++) {
                            u32 krow = 288u + (u32)(tap * 32 + s * 16) + lrow;
                            u32 bchunk = (u32)((h * 2 + j) * 2) + lsel;
                            ldsm_x4_t(bl[j], Bbase + krow * 128 + ((bchunk ^ (krow & 7)) << 4));
                        }
#pragma unroll
                        for (int mt = 0; mt < 2; mt++)
#pragma unroll
                            for (int nt = 0; nt < 4; nt++)
                                mma_bf16(C[mt][nt], ah[mt], &bl[nt >> 1][(nt & 1) * 2]);
                    }
                    {
                        u32 al[2][4];
#pragma unroll
                        for (int mt = 0; mt < 2; mt++) {
                            u32 arow = (u32)((2 * r + 1 + mt) * 16) + lrow + rowoff;
                            u32 achunk = 4u + (u32)(s * 2) + lsel;
                            ldsm_x4(al[mt], Abase + arow * 128 + ((achunk ^ (arow & 7)) << 4));
                        }
#pragma unroll
                        for (int mt = 0; mt < 2; mt++)
#pragma unroll
                            for (int nt = 0; nt < 4; nt++)
                                mma_bf16(C[mt][nt], al[mt], &bh[nt >> 1][(nt & 1) * 2]);
                    }
                }
            }

            // ---- epilogue: pool + bias + relu -> bf16 hi/lo planes ----
            __nv_bfloat16* xh = g_xhi + (size_t)img * 3136;
            __nv_bfloat16* xl = g_xlo + (size_t)img * 3136;
#pragma unroll
            for (int nt = 0; nt < 4; nt++) {
                const int ch = h * 32 + nt * 8 + 2 * kq;
                float p0 = fmaxf(C[0][nt][0], C[1][nt][0]);
                float p1 = fmaxf(C[0][nt][1], C[1][nt][1]);
                float p2 = fmaxf(C[0][nt][2], C[1][nt][2]);
                float p3 = fmaxf(C[0][nt][3], C[1][nt][3]);
                int srcl = (int)((lane + 4) & 31);
                float q0 = __shfl_sync(0xffffffffu, p0, srcl);
                float q1 = __shfl_sync(0xffffffffu, p1, srcl);
                float q2 = __shfl_sync(0xffffffffu, p2, srcl);
                float q3 = __shfl_sync(0xffffffffu, p3, srcl);
                float bx = s_bias[ch];
                float by = s_bias[ch + 1];

                if (g == 1 || g == 3 || g == 5) {
                    int pxo = (g - 1) >> 1;
                    float vx = fmaxf(fmaxf(p0, q0) + bx, 0.0f);
                    float vy = fmaxf(fmaxf(p1, q1) + by, 0.0f);
                    __nv_bfloat162 lv;
                    __nv_bfloat162 hv = bf2_hi(vx, vy, lv);
                    int o = (r * 7 + pxo) * 64 + ch;
                    *reinterpret_cast<__nv_bfloat162*>(xh + o) = hv;
                    *reinterpret_cast<__nv_bfloat162*>(xl + o) = lv;
                    vx = fmaxf(fmaxf(p2, q2) + bx, 0.0f);
                    vy = fmaxf(fmaxf(p3, q3) + by, 0.0f);
                    hv = bf2_hi(vx, vy, lv);
                    o = (r * 7 + pxo + 4) * 64 + ch;
                    *reinterpret_cast<__nv_bfloat162*>(xh + o) = hv;
                    *reinterpret_cast<__nv_bfloat162*>(xl + o) = lv;
                } else if (g == 7) {
                    float vx = fmaxf(fmaxf(p0, q2) + bx, 0.0f);
                    float vy = fmaxf(fmaxf(p1, q3) + by, 0.0f);
                    __nv_bfloat162 lv;
                    __nv_bfloat162 hv = bf2_hi(vx, vy, lv);
                    int o = (r * 7 + 3) * 64 + ch;
                    *reinterpret_cast<__nv_bfloat162*>(xh + o) = hv;
                    *reinterpret_cast<__nv_bfloat162*>(xl + o) = lv;
                }
            }
        }
        __syncthreads();
    }
}

// ---------------------------------------------------------------------------
// Kernel 3: FC via split-bf16 HMMA + fused MLR.
// Block = 64 images, 256 threads / 8 warps. warp = (mt 0..3, npair 0..1).
// C = Ah*Bh + Ah*Bl + Al*Bh, all into one fragment per warp.
// SMEM layout (bytes):
//   x_s   @0      64*33*4   = 8448
//   hw/hb @8448   2*320*4   = 2560
//   bias  @11008  128
//   A     @11264  128 rows * 464B = 59392   (rows: [hi 64 imgs | lo 64 imgs])
//   B     @70656  224 rows * 128B = 28672   -> total 99328
// ---------------------------------------------------------------------------
#define FC_XS_OFF   0
#define FC_HW_OFF   8448
#define FC_HB_OFF   (8448 + 1280)
#define FC_BIAS_OFF 11008
#define FC_A_OFF    11264
#define FC_AROW     464
#define FC_B_OFF    (FC_A_OFF + 128 * FC_AROW)    // 70656
#define FC_SMEM_BYTES (FC_B_OFF + 224 * 128)      // 99328

__global__ __launch_bounds__(256)
void fc_mlr_kernel(const float* __restrict__ bias,
                   const float* __restrict__ hw,
                   const float* __restrict__ hb,
                   float* __restrict__ out)
{
    extern __shared__ __align__(16) char smem[];
    const u32 sb   = smem_to_u32(smem);
    const int tid  = threadIdx.x;
    const int wrp  = tid >> 5;
    const int mt   = wrp & 3;
    const int np   = wrp >> 2;           // n-pair 0/1
    const u32 lane = tid & 31;
    const u32 lrow = lane & 15, lsel = lane >> 4;
    const int n0   = blockIdx.x * 64;

    float* x_s   = reinterpret_cast<float*>(smem + FC_XS_OFF);
    float* hw_s  = reinterpret_cast<float*>(smem + FC_HW_OFF);
    float* hb_s  = reinterpret_cast<float*>(smem + FC_HB_OFF);
    float* fcb_s = reinterpret_cast<float*>(smem + FC_BIAS_OFF);

    for (int i = tid; i < 320; i += 256) { hw_s[i] = hw[i]; hb_s[i] = hb[i]; }
    if (tid < 32) fcb_s[tid] = bias[tid];

    float C[2][4];
#pragma unroll
    for (int nt = 0; nt < 2; nt++)
#pragma unroll
        for (int q = 0; q < 4; q++) C[nt][q] = 0.0f;

#pragma unroll 1
    for (int kt = 0; kt < 14; kt++) {
        __syncthreads();
        // load A tile: 128 rows (hi imgs then lo imgs) x 28 chunks
        for (int i = tid; i < 128 * 28; i += 256) {
            int row = i / 28, c = i - row * 28;
            int plane = row >> 6, im = row & 63;
            const __nv_bfloat16* srcp = plane ? g_xlo : g_xhi;
            uint4 v = *reinterpret_cast<const uint4*>(
                srcp + (size_t)(n0 + im) * 3136 + kt * 224 + c * 8);
            *reinterpret_cast<uint4*>(smem + FC_A_OFF + row * FC_AROW + c * 16) = v;
        }
        // load B tile: 224 rows x 8 chunks (pre-swizzled source layout matches)
        for (int i = tid; i < 224 * 8; i += 256) {
            int krow = i >> 3, c = i & 7;
            // source is stored swizzled by global k' ; re-swizzle for local row
            int gk = kt * 224 + krow;
            uint4 v = *reinterpret_cast<const uint4*>(
                reinterpret_cast<const char*>(g_fcwbf) + gk * 128 + ((c ^ (gk & 7)) << 4));
            *reinterpret_cast<uint4*>(smem + FC_B_OFF + krow * 128 + ((c ^ (krow & 7)) << 4)) = v;
        }
        __syncthreads();

#pragma unroll 2
        for (int s = 0; s < 14; s++) {
            u32 ah[4], al[4], bh[4], bl[4];
            ldsm_x4(ah, sb + FC_A_OFF + (u32)((mt * 16 + lrow) * FC_AROW) + (u32)(s * 32) + lsel * 16);
            ldsm_x4(al, sb + FC_A_OFF + (u32)((64 + mt * 16 + lrow) * FC_AROW) + (u32)(s * 32) + lsel * 16);
            u32 krow = (u32)(s * 16) + lrow;
            u32 ch = (u32)(np * 2) + lsel;
            ldsm_x4_t(bh, sb + FC_B_OFF + krow * 128 + ((ch ^ (krow & 7)) << 4));
            u32 cl = 4u + (u32)(np * 2) + lsel;
            ldsm_x4_t(bl, sb + FC_B_OFF + krow * 128 + ((cl ^ (krow & 7)) << 4));
#pragma unroll
            for (int nt = 0; nt < 2; nt++) {
                mma_bf16(C[nt], ah, &bh[nt * 2]);
                mma_bf16(C[nt], ah, &bl[nt * 2]);
                mma_bf16(C[nt], al, &bh[nt * 2]);
            }
        }
    }

    // ---- stage x = C + fc_b into x_s ----
    {
        const int r0 = (int)(lane >> 2);
        const int cb = (int)(lane & 3) * 2;
#pragma unroll
        for (int nt = 0; nt < 2; nt++) {
            int col = np * 16 + nt * 8 + cb;
            float b0 = fcb_s[col], b1 = fcb_s[col + 1];
            x_s[(mt * 16 + r0) * 33 + col]         = C[nt][0] + b0;
            x_s[(mt * 16 + r0) * 33 + col + 1]     = C[nt][1] + b1;
            x_s[(mt * 16 + r0 + 8) * 33 + col]     = C[nt][2] + b0;
            x_s[(mt * 16 + r0 + 8) * 33 + col + 1] = C[nt][3] + b1;
        }
    }
    __syncthreads();

    // ---- MLR: 640 (n,k) pairs ----
    for (int i = tid; i < 640; i += 256) {
        int n = i / 10;
        int k = i - n * 10;
        const float* xv  = x_s + n * 33;
        const float* wv  = hw_s + k * 32;
        const float* bvv = hb_s + k * 32;

        float x2 = 0.f, b2 = 0.f, w2 = 0.f, xb = 0.f, xw = 0.f, wb = 0.f;
#pragma unroll
        for (int j = 0; j < 32; j++) {
            float xj = xv[j], wj = wv[j], bj = bvv[j];
            x2 += xj * xj;  b2 += bj * bj;  w2 += wj * wj;
            xb += xj * bj;  xw += xj * wj;  wb += wj * bj;
        }

        const float EPSf = 1e-5f;
        const float MN   = 0.99999f;

        float inner  = -xb;
        float w_norm = sqrtf(w2);
        float inv_wn = 1.0f / fmaxf(w_norm, 1e-12f);
        float wb_n   = -wb * inv_wn;
        float xw_n   = xw * inv_wn;

        float a_num = 1.0f + 2.0f * inner + x2;
        float b_num = 1.0f - b2;
        float denom = 1.0f + 2.0f * inner + x2 * b2;
        float alpha = a_num / fmaxf(denom, EPSf);
        float beta  = b_num / denom;
        float mob2  = alpha * alpha * b2 + 2.0f * alpha * beta * inner
                    + beta * beta * x2;
        float sq    = sqrtf(mob2);
        float normalizer = (sq > MN) ? (MN / fmaxf(sq, EPSf)) : 1.0f;
        float mob2f = (sq < MN) ? mob2 : (MN * MN);
        float hyp   = (alpha * wb_n + beta * xw_n) * normalizer;
        float asin_in = 2.0f * hyp / fmaxf(1.0f - mob2f, EPSf);

        out[(size_t)(n0 + n) * 10 + k] =
            (2.0f / fmaxf(1.0f - b2, EPSf)) * w_norm * asinhf(asin_in);
    }
}

// ---------------------------------------------------------------------------
// Launch
// ---------------------------------------------------------------------------
extern "C" void kernel_launch(void* const* d_in, const int* in_sizes, int n_in,
                              void* d_out, int out_size) {
    const float* x   = (const float*)d_in[0];
    const float* w1  = (const float*)d_in[1];
    const float* b1  = (const float*)d_in[2];
    const float* w2  = (const float*)d_in[3];
    const float* b2  = (const float*)d_in[4];
    const float* fw  = (const float*)d_in[5];
    const float* fb  = (const float*)d_in[6];
    const float* hw  = (const float*)d_in[7];
    const float* hb  = (const float*)d_in[8];
    float* out = (float*)d_out;

    const int N = in_sizes[0] / 784;

    cudaFuncSetAttribute(conv2_mma_kernel,
                         cudaFuncAttributeMaxDynamicSharedMemorySize,
                         C2_SMEM_BYTES);
    cudaFuncSetAttribute(fc_mlr_kernel,
                         cudaFuncAttributeMaxDynamicSharedMemorySize,
                         FC_SMEM_BYTES);

    prep_all<<<29, 1024>>>(w2, fw);
    conv1_kernel<<<N, 256>>>(x, w1, b1);
    int g2 = N < 296 ? N : 296;
    conv2_mma_kernel<<<g2, C2_THREADS, C2_SMEM_BYTES>>>(b2, N);
    fc_mlr_kernel<<<N / 64, 256, FC_SMEM_BYTES>>>(fb, hw, hb, out);
}